// round 6
// baseline (speedup 1.0000x reference)
#include <cuda_runtime.h>
#include <cuda_bf16.h>

#define C_IN  32
#define C_OUT 16
#define H_IN  256
#define W_IN  256
#define H_OUT 128
#define W_OUT 128
#define HW_IN  (H_IN * W_IN)     // 65536
#define HW_OUT (H_OUT * W_OUT)   // 16384

// One thread handles one (n, h2, w-pair): 2 adjacent output pixels across all
// 16 output channels. Input read as float4 (covers 4 input columns = 2 output
// columns) for 2 rows (the 2x2 pool window), per input channel.
__global__ __launch_bounds__(256) void fused_bn_relu_pool_conv(
    const float* __restrict__ x,      // [N, C_IN, H, W]
    const float* __restrict__ wgt,    // [C_IN, C_OUT]
    const float* __restrict__ scale,  // [C_IN]
    const float* __restrict__ bias,   // [C_IN]
    float* __restrict__ out)          // [N, C_OUT, H/2, W/2]
{
    // Weight rows as float4, pre-scaled by 0.25 (folds the 2x2 mean).
    __shared__ float4 sw[C_IN][C_OUT / 4];
    __shared__ float  ss[C_IN];
    __shared__ float  sb[C_IN];

    const int tid = threadIdx.x;
    // C_IN*C_OUT = 512 > blockDim = 256: strided cooperative load (R5 bugfix).
    for (int i = tid; i < C_IN * C_OUT; i += 256) {
        ((float*)sw)[i] = wgt[i] * 0.25f;
    }
    if (tid < C_IN) {
        ss[tid] = scale[tid];
        sb[tid] = bias[tid];
    }
    __syncthreads();

    const int gid = blockIdx.x * 256 + tid;       // 32 * 128 * 64 total
    const int wp  = gid & 63;                     // float4 column pair index
    const int h2  = (gid >> 6) & 127;             // output row
    const int n   = gid >> 13;                    // batch

    const float* xb = x + ((n * C_IN) * H_IN + 2 * h2) * W_IN + wp * 4;

    float acc0[C_OUT], acc1[C_OUT];
#pragma unroll
    for (int d = 0; d < C_OUT; d++) { acc0[d] = 0.0f; acc1[d] = 0.0f; }

#pragma unroll 4
    for (int c = 0; c < C_IN; c++) {
        const float4 r0 = *(const float4*)(xb + c * HW_IN);
        const float4 r1 = *(const float4*)(xb + c * HW_IN + W_IN);
        const float s = ss[c];
        const float b = sb[c];

        // BN affine -> ReLU -> sum over 2x2 window (x0.25 folded into weight)
        const float p0 = fmaxf(fmaf(r0.x, s, b), 0.0f) + fmaxf(fmaf(r0.y, s, b), 0.0f)
                       + fmaxf(fmaf(r1.x, s, b), 0.0f) + fmaxf(fmaf(r1.y, s, b), 0.0f);
        const float p1 = fmaxf(fmaf(r0.z, s, b), 0.0f) + fmaxf(fmaf(r0.w, s, b), 0.0f)
                       + fmaxf(fmaf(r1.z, s, b), 0.0f) + fmaxf(fmaf(r1.w, s, b), 0.0f);

#pragma unroll
        for (int q = 0; q < 4; q++) {
            const float4 w4 = sw[c][q];
            acc0[4 * q + 0] = fmaf(p0, w4.x, acc0[4 * q + 0]);
            acc0[4 * q + 1] = fmaf(p0, w4.y, acc0[4 * q + 1]);
            acc0[4 * q + 2] = fmaf(p0, w4.z, acc0[4 * q + 2]);
            acc0[4 * q + 3] = fmaf(p0, w4.w, acc0[4 * q + 3]);
            acc1[4 * q + 0] = fmaf(p1, w4.x, acc1[4 * q + 0]);
            acc1[4 * q + 1] = fmaf(p1, w4.y, acc1[4 * q + 1]);
            acc1[4 * q + 2] = fmaf(p1, w4.z, acc1[4 * q + 2]);
            acc1[4 * q + 3] = fmaf(p1, w4.w, acc1[4 * q + 3]);
        }
    }

    float* ob = out + (n * C_OUT * H_OUT + h2) * W_OUT + wp * 2;
#pragma unroll
    for (int d = 0; d < C_OUT; d++) {
        float2 v;
        v.x = acc0[d];
        v.y = acc1[d];
        *(float2*)(ob + d * HW_OUT) = v;
    }
}

extern "C" void kernel_launch(void* const* d_in, const int* in_sizes, int n_in,
                              void* d_out, int out_size) {
    const float* x     = (const float*)d_in[0];  // [32, 32, 256, 256]
    const float* wgt   = (const float*)d_in[1];  // [32, 16]
    const float* scale = (const float*)d_in[2];  // [32]
    const float* bias  = (const float*)d_in[3];  // [32]
    float* out = (float*)d_out;                  // [32, 16, 128, 128]

    // total threads = 32 (n) * 128 (h2) * 64 (w-pairs) = 262144
    const int threads = 256;
    const int blocks  = (32 * 128 * 64) / threads;  // 1024
    fused_bn_relu_pool_conv<<<blocks, threads>>>(x, wgt, scale, bias, out);
}

// round 9
// speedup vs baseline: 1.0705x; 1.0705x over previous
#include <cuda_runtime.h>
#include <cuda_bf16.h>

#define C_IN  32
#define C_OUT 16
#define H_IN  256
#define W_IN  256
#define H_OUT 128
#define W_OUT 128
#define HW_IN  (H_IN * W_IN)     // 65536
#define HW_OUT (H_OUT * W_OUT)   // 16384

// One thread = one output pixel (n, h2, w2), all 16 output channels.
// Per input channel: two float2 loads (the 2x2 pool window), BN+ReLU+sum,
// then a 16-wide rank-1 FMA update. acc[16] keeps regs low for occupancy.
__global__ __launch_bounds__(256) void fused_bn_relu_pool_conv(
    const float* __restrict__ x,      // [N, C_IN, H, W]
    const float* __restrict__ wgt,    // [C_IN, C_OUT]
    const float* __restrict__ scale,  // [C_IN]
    const float* __restrict__ bias,   // [C_IN]
    float* __restrict__ out)          // [N, C_OUT, H/2, W/2]
{
    // Weight rows as float4, pre-scaled by 0.25 (folds the 2x2 mean).
    __shared__ float4 sw[C_IN][C_OUT / 4];
    __shared__ float  ss[C_IN];
    __shared__ float  sb[C_IN];

    const int tid = threadIdx.x;
    for (int i = tid; i < C_IN * C_OUT; i += 256) {
        ((float*)sw)[i] = wgt[i] * 0.25f;
    }
    if (tid < C_IN) {
        ss[tid] = scale[tid];
        sb[tid] = bias[tid];
    }
    __syncthreads();

    const int gid = blockIdx.x * 256 + tid;   // 32 * 128 * 128 total
    const int w2  = gid & 127;                // output column
    const int h2  = (gid >> 7) & 127;         // output row
    const int n   = gid >> 14;                // batch

    const float* xb = x + ((n * C_IN) * H_IN + 2 * h2) * W_IN + 2 * w2;

    float acc[C_OUT];
#pragma unroll
    for (int d = 0; d < C_OUT; d++) acc[d] = 0.0f;

#pragma unroll 4
    for (int c = 0; c < C_IN; c++) {
        const float2 r0 = *(const float2*)(xb + c * HW_IN);
        const float2 r1 = *(const float2*)(xb + c * HW_IN + W_IN);
        const float s = ss[c];
        const float b = sb[c];

        // BN affine -> ReLU -> sum 2x2 window (x0.25 folded into weight)
        const float p = fmaxf(fmaf(r0.x, s, b), 0.0f) + fmaxf(fmaf(r0.y, s, b), 0.0f)
                      + fmaxf(fmaf(r1.x, s, b), 0.0f) + fmaxf(fmaf(r1.y, s, b), 0.0f);

#pragma unroll
        for (int q = 0; q < 4; q++) {
            const float4 w4 = sw[c][q];
            acc[4 * q + 0] = fmaf(p, w4.x, acc[4 * q + 0]);
            acc[4 * q + 1] = fmaf(p, w4.y, acc[4 * q + 1]);
            acc[4 * q + 2] = fmaf(p, w4.z, acc[4 * q + 2]);
            acc[4 * q + 3] = fmaf(p, w4.w, acc[4 * q + 3]);
        }
    }

    float* ob = out + (n * C_OUT * H_OUT + h2) * W_OUT + w2;
#pragma unroll
    for (int d = 0; d < C_OUT; d++) {
        ob[d * HW_OUT] = acc[d];
    }
}

extern "C" void kernel_launch(void* const* d_in, const int* in_sizes, int n_in,
                              void* d_out, int out_size) {
    const float* x     = (const float*)d_in[0];  // [32, 32, 256, 256]
    const float* wgt   = (const float*)d_in[1];  // [32, 16]
    const float* scale = (const float*)d_in[2];  // [32]
    const float* bias  = (const float*)d_in[3];  // [32]
    float* out = (float*)d_out;                  // [32, 16, 128, 128]

    // total threads = 32 (n) * 128 (h2) * 128 (w2) = 524288
    const int threads = 256;
    const int blocks  = (32 * 128 * 128) / threads;  // 2048
    fused_bn_relu_pool_conv<<<blocks, threads>>>(x, wgt, scale, bias, out);
}